// round 4
// baseline (speedup 1.0000x reference)
#include <cuda_runtime.h>
#include <cuda_bf16.h>
#include <cstdint>

// ============================================================================
// SVGD: phi_i = (r_i*mu - GP_i - (x_i*r_i - GP_i)/h^2) / N
// When h^2 == 1 the GP terms cancel: phi_i = r_i*(mu - x_i)/N, so only the
// gram row-sum is needed. Fast path: bf16 HMMA (mma.sync.m16n8k16) S = X X^T
// with fp32 accumulation + exact diagonal fix (g_ii = 1), split-j across 4
// CTAs per row-block with an in-kernel atomic-counter fixup that writes the
// final output (no separate finish kernel). Generic-h path: proven fp32
// fused kernel (early-exits when the fast path is active).
// NOTE: tcgen05 does NOT assemble under this harness's PTX target (plain
// sm_100); ldmatrix/mma.sync/cp.async do.
// ============================================================================

#define D       128
#define NMAX    4096
#define JSPLIT  4
#define JSLICE  (NMAX / JSPLIT)   // 1024
#define NT      (JSLICE / 128)    // 8 j-subtiles per CTA
#define LOG2E   1.4426950408889634f

__device__ float         g_sq[NMAX];
__device__ __nv_bfloat16 g_xbf[NMAX * D];
__device__ float         g_rpart[JSPLIT][NMAX];
__device__ unsigned int  g_ctr[NMAX / 128];   // wraps 3->0: self-resets per replay

// ---------------------------------------------------------------------------
// PTX helpers
// ---------------------------------------------------------------------------
__device__ __forceinline__ uint32_t smem_u32(const void* p) {
    uint32_t a;
    asm("{ .reg .u64 t; cvta.to.shared.u64 t, %1; cvt.u32.u64 %0, t; }"
        : "=r"(a) : "l"(p));
    return a;
}
__device__ __forceinline__ void cp16(uint32_t dst, const void* src) {
    asm volatile("cp.async.cg.shared.global [%0], [%1], 16;" :: "r"(dst), "l"(src));
}
#define CP_COMMIT() asm volatile("cp.async.commit_group;" ::: "memory")
#define CP_WAIT0()  asm volatile("cp.async.wait_group 0;" ::: "memory")

__device__ __forceinline__ void ldsm4(uint32_t* r, uint32_t addr) {
    asm volatile("ldmatrix.sync.aligned.m8n8.x4.shared.b16 {%0,%1,%2,%3}, [%4];"
                 : "=r"(r[0]), "=r"(r[1]), "=r"(r[2]), "=r"(r[3]) : "r"(addr));
}
__device__ __forceinline__ void mma_bf16(float* c, const uint32_t* a,
                                         uint32_t b0, uint32_t b1) {
    asm volatile("mma.sync.aligned.m16n8k16.row.col.f32.bf16.bf16.f32 "
                 "{%0,%1,%2,%3}, {%4,%5,%6,%7}, {%8,%9}, {%0,%1,%2,%3};"
                 : "+f"(c[0]), "+f"(c[1]), "+f"(c[2]), "+f"(c[3])
                 : "r"(a[0]), "r"(a[1]), "r"(a[2]), "r"(a[3]), "r"(b0), "r"(b1));
}
__device__ __forceinline__ float exp2a(float x) {
    float g;
    asm("ex2.approx.ftz.f32 %0, %1;" : "=f"(g) : "f"(x));
    return g;
}

// ---------------------------------------------------------------------------
// Kernel 1: |x_i|^2 + bf16 copy of X. One warp per row.
// ---------------------------------------------------------------------------
__global__ void prep_kernel(const float* __restrict__ P, int n) {
    int warp = (blockIdx.x * blockDim.x + threadIdx.x) >> 5;
    int lane = threadIdx.x & 31;
    if (warp >= n) return;
    float4 v = *((const float4*)(P + warp * D) + lane);
    float s = v.x * v.x + v.y * v.y + v.z * v.z + v.w * v.w;
    #pragma unroll
    for (int o = 16; o > 0; o >>= 1) s += __shfl_xor_sync(0xffffffffu, s, o);
    if (lane == 0) g_sq[warp] = s;
    __nv_bfloat162 p0 = __floats2bfloat162_rn(v.x, v.y);
    __nv_bfloat162 p1 = __floats2bfloat162_rn(v.z, v.w);
    ((__nv_bfloat162*)g_xbf)[warp * 64 + lane * 2 + 0] = p0;
    ((__nv_bfloat162*)g_xbf)[warp * 64 + lane * 2 + 1] = p1;
}

// ---------------------------------------------------------------------------
// HMMA fast path (h^2==1): r_i = sum_j exp((2 S_ij - sq_i - sq_j)/2), diag = 1.
// grid (32, JSPLIT), 256 threads. Warp layout: 2 (m, 64 rows) x 4 (n, 32 cols).
// SMEM tiles: 128 rows x 256B, 16B chunks XOR-swizzled (c ^ (r&7)).
// Last CTA per row-block performs the split-j fixup and writes out.
// ---------------------------------------------------------------------------
#define SM_XI    0
#define SM_XJ0   32768
#define SM_XJ1   65536
#define SM_RBUF  98304           // 128 floats
#define SM_CSL   98816           // 1024 floats
#define SM_TOTAL 102912

__device__ __forceinline__ void load_tile_async(uint32_t dst_sb, int src_row, int tid) {
    const char* src = (const char*)(g_xbf + (size_t)src_row * D);
    #pragma unroll
    for (int tt = 0; tt < 8; ++tt) {
        int lin = tt * 256 + tid;
        int r = lin >> 4, c = lin & 15;
        cp16(dst_sb + r * 256 + ((c ^ (r & 7)) << 4), src + r * 256 + c * 16);
    }
}

__global__ __launch_bounds__(256, 1)
void svgd_hmma_kernel(const float* __restrict__ P, const float* __restrict__ mu,
                      const float* __restrict__ bw, float* __restrict__ out) {
    const float h2 = bw[0] * bw[0];
    if (h2 != 1.0f) return;          // generic h handled by fp32 kernel

    extern __shared__ char smem[];
    const uint32_t sb = smem_u32(smem);
    float* rbuf = (float*)(smem + SM_RBUF);
    float* csl  = (float*)(smem + SM_CSL);
    __shared__ unsigned int s_old;

    const int tid   = threadIdx.x;
    const int wid   = tid >> 5;
    const int lane  = tid & 31;
    const int wm    = wid & 1;       // m half (64 rows)
    const int wn    = wid >> 1;      // n quarter (32 cols)
    const int bi    = blockIdx.x;
    const int row0  = bi * 128;
    const int jbase = blockIdx.y * JSLICE;

    const float k2    = (0.5f / h2) * LOG2E;
    const float twok2 = 2.0f * k2;

    if (tid < 128) rbuf[tid] = 0.0f;
    for (int j = tid; j < JSLICE; j += 256) csl[j] = -g_sq[jbase + j] * k2;

    load_tile_async(sb + SM_XI, row0, tid);
    load_tile_async(sb + SM_XJ0, jbase, tid);
    CP_COMMIT();

    // per-thread row constants: rows wm*64 + mt*16 + (lane>>2) + {0,8}
    const int r_in = lane >> 2;
    const int c2   = (lane & 3) * 2;
    float cti[8], rp[8];
    #pragma unroll
    for (int i = 0; i < 8; ++i) {
        int rloc = wm * 64 + (i >> 1) * 16 + r_in + (i & 1) * 8;
        cti[i] = -g_sq[row0 + rloc] * k2;
        rp[i]  = 0.0f;
    }

    CP_WAIT0();
    __syncthreads();

    const uint32_t xi_base = sb + SM_XI + (uint32_t)(wm * 64) * 256;
    const uint32_t lrow16  = (uint32_t)(lane & 15) * 256;
    const uint32_t lswz    = (uint32_t)(lane & 7);
    const uint32_t lkhalf  = (uint32_t)(lane >> 4);

    for (int t = 0; t < NT; ++t) {
        const uint32_t cur_off = (t & 1) ? SM_XJ1 : SM_XJ0;
        if (t + 1 < NT) {
            load_tile_async(sb + ((t & 1) ? SM_XJ0 : SM_XJ1), jbase + (t + 1) * 128, tid);
            CP_COMMIT();
        }
        const uint32_t xj_base = sb + cur_off + (uint32_t)(wn * 32) * 256;

        // ---- S tile: 128 HMMA per warp, K=128 in 8 steps ----
        float acc[4][4][4];
        #pragma unroll
        for (int mt = 0; mt < 4; ++mt)
            #pragma unroll
            for (int nt = 0; nt < 4; ++nt)
                #pragma unroll
                for (int q = 0; q < 4; ++q) acc[mt][nt][q] = 0.0f;

        #pragma unroll
        for (int kk = 0; kk < 8; ++kk) {
            const uint32_t swz = (((uint32_t)(2 * kk) + lkhalf) ^ lswz) << 4;
            uint32_t a[4][4], b[2][4];
            #pragma unroll
            for (int mt = 0; mt < 4; ++mt)
                ldsm4(a[mt], xi_base + (uint32_t)(mt * 16) * 256 + lrow16 + swz);
            #pragma unroll
            for (int bt = 0; bt < 2; ++bt)
                ldsm4(b[bt], xj_base + (uint32_t)(bt * 16) * 256 + lrow16 + swz);
            #pragma unroll
            for (int mt = 0; mt < 4; ++mt) {
                mma_bf16(acc[mt][0], a[mt], b[0][0], b[0][2]);
                mma_bf16(acc[mt][1], a[mt], b[0][1], b[0][3]);
                mma_bf16(acc[mt][2], a[mt], b[1][0], b[1][2]);
                mma_bf16(acc[mt][3], a[mt], b[1][1], b[1][3]);
            }
        }

        // ---- epilogue: g = exp2((2S - sqi - sqj)*log2e/2), diag forced 1 ----
        const bool diag = (jbase + t * 128 == row0);
        #pragma unroll
        for (int mt = 0; mt < 4; ++mt) {
            const int rloc0 = wm * 64 + mt * 16 + r_in;
            const int rloc1 = rloc0 + 8;
            const float ct0 = cti[mt * 2], ct1 = cti[mt * 2 + 1];
            #pragma unroll
            for (int nt = 0; nt < 4; ++nt) {
                const int cloc = wn * 32 + nt * 8 + c2;
                float2 cs = *(float2*)(csl + t * 128 + cloc);
                float g0 = exp2a(fmaf(acc[mt][nt][0], twok2, ct0 + cs.x));
                float g1 = exp2a(fmaf(acc[mt][nt][1], twok2, ct0 + cs.y));
                float g2 = exp2a(fmaf(acc[mt][nt][2], twok2, ct1 + cs.x));
                float g3 = exp2a(fmaf(acc[mt][nt][3], twok2, ct1 + cs.y));
                if (diag) {
                    if (rloc0 == cloc)     g0 = 1.0f;
                    if (rloc0 == cloc + 1) g1 = 1.0f;
                    if (rloc1 == cloc)     g2 = 1.0f;
                    if (rloc1 == cloc + 1) g3 = 1.0f;
                }
                rp[mt * 2]     += g0 + g1;
                rp[mt * 2 + 1] += g2 + g3;
            }
        }

        if (t + 1 < NT) CP_WAIT0();
        __syncthreads();
    }

    // ---- reduce across the 4 column lanes, then across n-warps via smem ----
    #pragma unroll
    for (int i = 0; i < 8; ++i) {
        rp[i] += __shfl_xor_sync(0xffffffffu, rp[i], 1);
        rp[i] += __shfl_xor_sync(0xffffffffu, rp[i], 2);
    }
    if ((lane & 3) == 0) {
        #pragma unroll
        for (int i = 0; i < 8; ++i) {
            int rloc = wm * 64 + (i >> 1) * 16 + r_in + (i & 1) * 8;
            atomicAdd(&rbuf[rloc], rp[i]);
        }
    }
    __syncthreads();
    if (tid < 128) g_rpart[blockIdx.y][row0 + tid] = rbuf[tid];

    // ---- split-j fixup: last CTA of this row-block writes the output ----
    __threadfence();                 // make this CTA's g_rpart writes visible
    __syncthreads();
    if (tid == 0) s_old = atomicInc(&g_ctr[bi], 3u);   // wraps 3 -> 0
    __syncthreads();
    if (s_old == 3u) {
        __threadfence();             // observe the other CTAs' g_rpart writes
        const float invn = 1.0f / (float)NMAX;
        for (int e = tid; e < 128 * 32; e += 256) {
            int rr = e >> 5;
            int c4 = (e & 31) * 4;
            float r = g_rpart[0][row0 + rr] + g_rpart[1][row0 + rr]
                    + g_rpart[2][row0 + rr] + g_rpart[3][row0 + rr];
            float s = r * invn;
            float4 xv = *(const float4*)(P  + (row0 + rr) * D + c4);
            float4 mv = *(const float4*)(mu + c4);
            float4 o;
            o.x = (mv.x - xv.x) * s;
            o.y = (mv.y - xv.y) * s;
            o.z = (mv.z - xv.z) * s;
            o.w = (mv.w - xv.w) * s;
            *(float4*)(out + (row0 + rr) * D + c4) = o;
        }
    }
}

// ---------------------------------------------------------------------------
// Generic-h fp32 fallback (proven R1 kernel). Early-exits when h^2==1.
// ---------------------------------------------------------------------------
#define BM        32
#define BN        128
#define NTHREADS  256
#define XI_STRIDE 132
#define XJ_STRIDE 132
#define GS_STRIDE 132

__global__ __launch_bounds__(NTHREADS, 1)
void svgd_fp32_kernel(const float* __restrict__ P, const float* __restrict__ mu,
                      const float* __restrict__ bw, float* __restrict__ out,
                      int n, int tensor_active) {
    const float h2 = bw[0] * bw[0];
    if (tensor_active && h2 == 1.0f) return;

    extern __shared__ float sm[];
    float* Xi     = sm;
    float* Xj     = Xi + BM * XI_STRIDE;
    float* Gs     = Xj + BN * XJ_STRIDE;
    float* rowsum = Gs + BM * GS_STRIDE;

    const int tid  = threadIdx.x;
    const int row0 = blockIdx.x * BM;
    const float inv2h2 = 1.0f / (2.0f * h2);
    const float invh2  = 1.0f / h2;

    #pragma unroll
    for (int t = 0; t < (BM * D / 4) / NTHREADS; ++t) {
        int lin = t * NTHREADS + tid;
        int r = lin >> 5, c4 = lin & 31;
        *(float4*)(Xi + r * XI_STRIDE + c4 * 4) =
            *(const float4*)(P + (row0 + r) * D + c4 * 4);
    }

    const int rg  = tid >> 5, cg  = tid & 31;
    const int rg2 = tid >> 4, cg2 = tid & 15;

    float acc[2][8];
    #pragma unroll
    for (int i = 0; i < 2; i++)
        #pragma unroll
        for (int u = 0; u < 8; u++) acc[i][u] = 0.0f;
    float rs[4] = {0.f, 0.f, 0.f, 0.f};

    float sqi[4];
    #pragma unroll
    for (int i = 0; i < 4; i++) sqi[i] = g_sq[row0 + 4 * rg + i];

    const int ntiles = n / BN;
    for (int tile = 0; tile < ntiles; ++tile) {
        __syncthreads();
        const int j0 = tile * BN;
        #pragma unroll
        for (int t = 0; t < 16; ++t) {
            int lin = t * NTHREADS + tid;
            int r = lin >> 5, c4 = lin & 31;
            *(float4*)(Xj + r * XJ_STRIDE + c4 * 4) =
                *(const float4*)(P + (j0 + r) * D + c4 * 4);
        }
        __syncthreads();

        float s[4][4];
        #pragma unroll
        for (int i = 0; i < 4; i++)
            #pragma unroll
            for (int j = 0; j < 4; j++) s[i][j] = 0.0f;

        #pragma unroll 4
        for (int k4 = 0; k4 < 32; ++k4) {
            float4 a[4], b[4];
            #pragma unroll
            for (int i = 0; i < 4; i++)
                a[i] = *(const float4*)(Xi + (4 * rg + i) * XI_STRIDE + k4 * 4);
            #pragma unroll
            for (int j = 0; j < 4; j++)
                b[j] = *(const float4*)(Xj + (cg + 32 * j) * XJ_STRIDE + k4 * 4);
            #pragma unroll
            for (int i = 0; i < 4; i++)
                #pragma unroll
                for (int j = 0; j < 4; j++)
                    s[i][j] += a[i].x * b[j].x + a[i].y * b[j].y
                             + a[i].z * b[j].z + a[i].w * b[j].w;
        }

        float sqj[4];
        #pragma unroll
        for (int j = 0; j < 4; j++) sqj[j] = g_sq[j0 + cg + 32 * j];
        #pragma unroll
        for (int i = 0; i < 4; i++)
            #pragma unroll
            for (int j = 0; j < 4; j++) {
                float g = __expf((2.0f * s[i][j] - sqi[i] - sqj[j]) * inv2h2);
                rs[i] += g;
                Gs[(4 * rg + i) * GS_STRIDE + (cg + 32 * j)] = g;
            }
        __syncthreads();

        #pragma unroll 8
        for (int jj = 0; jj < BN; ++jj) {
            float g0 = Gs[(2 * rg2 + 0) * GS_STRIDE + jj];
            float g1 = Gs[(2 * rg2 + 1) * GS_STRIDE + jj];
            #pragma unroll
            for (int u = 0; u < 8; u++) {
                float x = Xj[jj * XJ_STRIDE + cg2 + 16 * u];
                acc[0][u] += g0 * x;
                acc[1][u] += g1 * x;
            }
        }
    }

    #pragma unroll
    for (int i = 0; i < 4; i++)
        #pragma unroll
        for (int o = 16; o > 0; o >>= 1)
            rs[i] += __shfl_xor_sync(0xffffffffu, rs[i], o);
    if (cg == 0)
        #pragma unroll
        for (int i = 0; i < 4; i++) rowsum[4 * rg + i] = rs[i];
    __syncthreads();

    const float invn = 1.0f / (float)n;
    #pragma unroll
    for (int i = 0; i < 2; i++) {
        int r = 2 * rg2 + i;
        float rsum = rowsum[r];
        #pragma unroll
        for (int u = 0; u < 8; u++) {
            int c = cg2 + 16 * u;
            float GP = acc[i][u];
            float x  = Xi[r * XI_STRIDE + c];
            out[(row0 + r) * D + c] =
                (rsum * mu[c] - GP - (x * rsum - GP) * invh2) * invn;
        }
    }
}

// ---------------------------------------------------------------------------
extern "C" void kernel_launch(void* const* d_in, const int* in_sizes, int n_in,
                              void* d_out, int out_size) {
    const float* P  = (const float*)d_in[0];
    const float* mu = (const float*)d_in[1];
    const float* bw = (const float*)d_in[2];
    float* out = (float*)d_out;
    const int n = in_sizes[0] / D;
    const int fast_ok = (n == NMAX) ? 1 : 0;

    const size_t fp32_smem =
        (size_t)(BM * XI_STRIDE + BN * XJ_STRIDE + BM * GS_STRIDE + BM) * sizeof(float);
    cudaFuncSetAttribute(svgd_fp32_kernel, cudaFuncAttributeMaxDynamicSharedMemorySize,
                         (int)fp32_smem);
    cudaFuncSetAttribute(svgd_hmma_kernel, cudaFuncAttributeMaxDynamicSharedMemorySize,
                         SM_TOTAL);

    prep_kernel<<<(n + 7) / 8, 256>>>(P, n);
    svgd_fp32_kernel<<<n / BM, NTHREADS, fp32_smem>>>(P, mu, bw, out, n, fast_ok);
    if (fast_ok) {
        svgd_hmma_kernel<<<dim3(NMAX / 128, JSPLIT), 256, SM_TOTAL>>>(P, mu, bw, out);
    }
}

// round 5
// speedup vs baseline: 1.2133x; 1.2133x over previous
#include <cuda_runtime.h>
#include <cuda_bf16.h>
#include <cstdint>

// ============================================================================
// SVGD: phi_i = (r_i*mu - GP_i - (x_i*r_i - GP_i)/h^2) / N
// When h^2 == 1 the GP terms cancel: phi_i = r_i*(mu - x_i)/N, so only the
// gram row-sum is needed. Fast path: bf16 HMMA (mma.sync.m16n8k16) S = X X^T
// with fp32 accumulation + exact diagonal fix (g_ii = 1). Generic-h path:
// proven fp32 fused kernel (early-exits when the fast path is active).
// R5: revert R4's fused fixup (serial-tail regression); MLP-4 prep; float4
// finish. tcgen05 does NOT assemble under this harness (plain sm_100 target).
// ============================================================================

#define D       128
#define NMAX    4096
#define JSPLIT  4
#define JSLICE  (NMAX / JSPLIT)   // 1024
#define NT      (JSLICE / 128)    // 8 j-subtiles per CTA
#define LOG2E   1.4426950408889634f

__device__ float         g_sq[NMAX];
__device__ __nv_bfloat16 g_xbf[NMAX * D];
__device__ float         g_rpart[JSPLIT][NMAX];

// ---------------------------------------------------------------------------
// PTX helpers
// ---------------------------------------------------------------------------
__device__ __forceinline__ uint32_t smem_u32(const void* p) {
    uint32_t a;
    asm("{ .reg .u64 t; cvta.to.shared.u64 t, %1; cvt.u32.u64 %0, t; }"
        : "=r"(a) : "l"(p));
    return a;
}
__device__ __forceinline__ void cp16(uint32_t dst, const void* src) {
    asm volatile("cp.async.cg.shared.global [%0], [%1], 16;" :: "r"(dst), "l"(src));
}
#define CP_COMMIT() asm volatile("cp.async.commit_group;" ::: "memory")
#define CP_WAIT0()  asm volatile("cp.async.wait_group 0;" ::: "memory")

__device__ __forceinline__ void ldsm4(uint32_t* r, uint32_t addr) {
    asm volatile("ldmatrix.sync.aligned.m8n8.x4.shared.b16 {%0,%1,%2,%3}, [%4];"
                 : "=r"(r[0]), "=r"(r[1]), "=r"(r[2]), "=r"(r[3]) : "r"(addr));
}
__device__ __forceinline__ void mma_bf16(float* c, const uint32_t* a,
                                         uint32_t b0, uint32_t b1) {
    asm volatile("mma.sync.aligned.m16n8k16.row.col.f32.bf16.bf16.f32 "
                 "{%0,%1,%2,%3}, {%4,%5,%6,%7}, {%8,%9}, {%0,%1,%2,%3};"
                 : "+f"(c[0]), "+f"(c[1]), "+f"(c[2]), "+f"(c[3])
                 : "r"(a[0]), "r"(a[1]), "r"(a[2]), "r"(a[3]), "r"(b0), "r"(b1));
}
__device__ __forceinline__ float exp2a(float x) {
    float g;
    asm("ex2.approx.ftz.f32 %0, %1;" : "=f"(g) : "f"(x));
    return g;
}

// ---------------------------------------------------------------------------
// Kernel 1: |x_i|^2 + bf16 copy of X. One warp per 4 rows, loads front-
// batched for MLP=4 (the R4 profile showed MLP=1 latency-bound at 4.7us).
// ---------------------------------------------------------------------------
__global__ void prep_kernel(const float* __restrict__ P, int n) {
    const int warp = (blockIdx.x * blockDim.x + threadIdx.x) >> 5;
    const int lane = threadIdx.x & 31;
    const int row0 = warp * 4;
    if (row0 >= n) return;

    float4 v[4];
    #pragma unroll
    for (int r = 0; r < 4; ++r)                       // 4 independent LDG.128
        v[r] = *((const float4*)(P + (row0 + r) * D) + lane);

    float s[4];
    #pragma unroll
    for (int r = 0; r < 4; ++r)
        s[r] = v[r].x * v[r].x + v[r].y * v[r].y + v[r].z * v[r].z + v[r].w * v[r].w;

    #pragma unroll
    for (int o = 16; o > 0; o >>= 1) {                // 4 interleaved chains
        #pragma unroll
        for (int r = 0; r < 4; ++r)
            s[r] += __shfl_xor_sync(0xffffffffu, s[r], o);
    }
    if (lane < 4) g_sq[row0 + lane] = s[lane];

    #pragma unroll
    for (int r = 0; r < 4; ++r) {
        __nv_bfloat162 p0 = __floats2bfloat162_rn(v[r].x, v[r].y);
        __nv_bfloat162 p1 = __floats2bfloat162_rn(v[r].z, v[r].w);
        ((__nv_bfloat162*)g_xbf)[(row0 + r) * 64 + lane * 2 + 0] = p0;
        ((__nv_bfloat162*)g_xbf)[(row0 + r) * 64 + lane * 2 + 1] = p1;
    }
}

// ---------------------------------------------------------------------------
// HMMA fast path (h^2==1): r_i = sum_j exp((2 S_ij - sq_i - sq_j)/2), diag = 1.
// grid (32, JSPLIT), 256 threads. Warp layout: 2 (m, 64 rows) x 4 (n, 32 cols).
// SMEM tiles: 128 rows x 256B, 16B chunks XOR-swizzled (c ^ (r&7)).
// ---------------------------------------------------------------------------
#define SM_XI    0
#define SM_XJ0   32768
#define SM_XJ1   65536
#define SM_RBUF  98304           // 128 floats
#define SM_CSL   98816           // 1024 floats
#define SM_TOTAL 102912

__device__ __forceinline__ void load_tile_async(uint32_t dst_sb, int src_row, int tid) {
    const char* src = (const char*)(g_xbf + (size_t)src_row * D);
    #pragma unroll
    for (int tt = 0; tt < 8; ++tt) {
        int lin = tt * 256 + tid;
        int r = lin >> 4, c = lin & 15;
        cp16(dst_sb + r * 256 + ((c ^ (r & 7)) << 4), src + r * 256 + c * 16);
    }
}

__global__ __launch_bounds__(256, 1)
void svgd_hmma_kernel(const float* __restrict__ bw) {
    const float h2 = bw[0] * bw[0];
    if (h2 != 1.0f) return;          // generic h handled by fp32 kernel

    extern __shared__ char smem[];
    const uint32_t sb = smem_u32(smem);
    float* rbuf = (float*)(smem + SM_RBUF);
    float* csl  = (float*)(smem + SM_CSL);

    const int tid   = threadIdx.x;
    const int wid   = tid >> 5;
    const int lane  = tid & 31;
    const int wm    = wid & 1;       // m half (64 rows)
    const int wn    = wid >> 1;      // n quarter (32 cols)
    const int row0  = blockIdx.x * 128;
    const int jbase = blockIdx.y * JSLICE;

    const float k2    = (0.5f / h2) * LOG2E;
    const float twok2 = 2.0f * k2;

    if (tid < 128) rbuf[tid] = 0.0f;
    for (int j = tid; j < JSLICE; j += 256) csl[j] = -g_sq[jbase + j] * k2;

    load_tile_async(sb + SM_XI, row0, tid);
    load_tile_async(sb + SM_XJ0, jbase, tid);
    CP_COMMIT();

    // per-thread row constants: rows wm*64 + mt*16 + (lane>>2) + {0,8}
    const int r_in = lane >> 2;
    const int c2   = (lane & 3) * 2;
    float cti[8], rp[8];
    #pragma unroll
    for (int i = 0; i < 8; ++i) {
        int rloc = wm * 64 + (i >> 1) * 16 + r_in + (i & 1) * 8;
        cti[i] = -g_sq[row0 + rloc] * k2;
        rp[i]  = 0.0f;
    }

    CP_WAIT0();
    __syncthreads();

    const uint32_t xi_base = sb + SM_XI + (uint32_t)(wm * 64) * 256;
    const uint32_t lrow16  = (uint32_t)(lane & 15) * 256;
    const uint32_t lswz    = (uint32_t)(lane & 7);
    const uint32_t lkhalf  = (uint32_t)(lane >> 4);

    for (int t = 0; t < NT; ++t) {
        const uint32_t cur_off = (t & 1) ? SM_XJ1 : SM_XJ0;
        if (t + 1 < NT) {
            load_tile_async(sb + ((t & 1) ? SM_XJ0 : SM_XJ1), jbase + (t + 1) * 128, tid);
            CP_COMMIT();
        }
        const uint32_t xj_base = sb + cur_off + (uint32_t)(wn * 32) * 256;

        // ---- S tile: 128 HMMA per warp, K=128 in 8 steps ----
        float acc[4][4][4];
        #pragma unroll
        for (int mt = 0; mt < 4; ++mt)
            #pragma unroll
            for (int nt = 0; nt < 4; ++nt)
                #pragma unroll
                for (int q = 0; q < 4; ++q) acc[mt][nt][q] = 0.0f;

        #pragma unroll
        for (int kk = 0; kk < 8; ++kk) {
            const uint32_t swz = (((uint32_t)(2 * kk) + lkhalf) ^ lswz) << 4;
            uint32_t a[4][4], b[2][4];
            #pragma unroll
            for (int mt = 0; mt < 4; ++mt)
                ldsm4(a[mt], xi_base + (uint32_t)(mt * 16) * 256 + lrow16 + swz);
            #pragma unroll
            for (int bt = 0; bt < 2; ++bt)
                ldsm4(b[bt], xj_base + (uint32_t)(bt * 16) * 256 + lrow16 + swz);
            #pragma unroll
            for (int mt = 0; mt < 4; ++mt) {
                mma_bf16(acc[mt][0], a[mt], b[0][0], b[0][2]);
                mma_bf16(acc[mt][1], a[mt], b[0][1], b[0][3]);
                mma_bf16(acc[mt][2], a[mt], b[1][0], b[1][2]);
                mma_bf16(acc[mt][3], a[mt], b[1][1], b[1][3]);
            }
        }

        // ---- epilogue: g = exp2((2S - sqi - sqj)*log2e/2), diag forced 1 ----
        const bool diag = (jbase + t * 128 == row0);
        #pragma unroll
        for (int mt = 0; mt < 4; ++mt) {
            const int rloc0 = wm * 64 + mt * 16 + r_in;
            const int rloc1 = rloc0 + 8;
            const float ct0 = cti[mt * 2], ct1 = cti[mt * 2 + 1];
            #pragma unroll
            for (int nt = 0; nt < 4; ++nt) {
                const int cloc = wn * 32 + nt * 8 + c2;
                float2 cs = *(float2*)(csl + t * 128 + cloc);
                float g0 = exp2a(fmaf(acc[mt][nt][0], twok2, ct0 + cs.x));
                float g1 = exp2a(fmaf(acc[mt][nt][1], twok2, ct0 + cs.y));
                float g2 = exp2a(fmaf(acc[mt][nt][2], twok2, ct1 + cs.x));
                float g3 = exp2a(fmaf(acc[mt][nt][3], twok2, ct1 + cs.y));
                if (diag) {
                    if (rloc0 == cloc)     g0 = 1.0f;
                    if (rloc0 == cloc + 1) g1 = 1.0f;
                    if (rloc1 == cloc)     g2 = 1.0f;
                    if (rloc1 == cloc + 1) g3 = 1.0f;
                }
                rp[mt * 2]     += g0 + g1;
                rp[mt * 2 + 1] += g2 + g3;
            }
        }

        if (t + 1 < NT) CP_WAIT0();
        __syncthreads();
    }

    // ---- reduce across the 4 column lanes, then across n-warps via smem ----
    #pragma unroll
    for (int i = 0; i < 8; ++i) {
        rp[i] += __shfl_xor_sync(0xffffffffu, rp[i], 1);
        rp[i] += __shfl_xor_sync(0xffffffffu, rp[i], 2);
    }
    if ((lane & 3) == 0) {
        #pragma unroll
        for (int i = 0; i < 8; ++i) {
            int rloc = wm * 64 + (i >> 1) * 16 + r_in + (i & 1) * 8;
            atomicAdd(&rbuf[rloc], rp[i]);
        }
    }
    __syncthreads();
    if (tid < 128) g_rpart[blockIdx.y][row0 + tid] = rbuf[tid];
}

// ---------------------------------------------------------------------------
// Finish (h^2 == 1): out = r * (mu - x) / n. One float4 per thread.
// ---------------------------------------------------------------------------
__global__ void finish_kernel(const float* __restrict__ P, const float* __restrict__ mu,
                              const float* __restrict__ bw, float* __restrict__ out, int n) {
    float h2 = bw[0] * bw[0];
    if (h2 != 1.0f) return;
    int gid = blockIdx.x * blockDim.x + threadIdx.x;   // float4 index
    if (gid >= n * (D / 4)) return;
    int i  = gid >> 5;          // row (32 float4 per row)
    int c4 = (gid & 31) * 4;
    float r = g_rpart[0][i] + g_rpart[1][i] + g_rpart[2][i] + g_rpart[3][i];
    float s = r * (1.0f / (float)n);
    float4 xv = *(const float4*)(P  + i * D + c4);
    float4 mv = *(const float4*)(mu + c4);
    float4 o;
    o.x = (mv.x - xv.x) * s;
    o.y = (mv.y - xv.y) * s;
    o.z = (mv.z - xv.z) * s;
    o.w = (mv.w - xv.w) * s;
    *(float4*)(out + i * D + c4) = o;
}

// ---------------------------------------------------------------------------
// Generic-h fp32 fallback (proven R1 kernel). Early-exits when h^2==1.
// ---------------------------------------------------------------------------
#define BM        32
#define BN        128
#define NTHREADS  256
#define XI_STRIDE 132
#define XJ_STRIDE 132
#define GS_STRIDE 132

__global__ __launch_bounds__(NTHREADS, 1)
void svgd_fp32_kernel(const float* __restrict__ P, const float* __restrict__ mu,
                      const float* __restrict__ bw, float* __restrict__ out,
                      int n, int tensor_active) {
    const float h2 = bw[0] * bw[0];
    if (tensor_active && h2 == 1.0f) return;

    extern __shared__ float sm[];
    float* Xi     = sm;
    float* Xj     = Xi + BM * XI_STRIDE;
    float* Gs     = Xj + BN * XJ_STRIDE;
    float* rowsum = Gs + BM * GS_STRIDE;

    const int tid  = threadIdx.x;
    const int row0 = blockIdx.x * BM;
    const float inv2h2 = 1.0f / (2.0f * h2);
    const float invh2  = 1.0f / h2;

    #pragma unroll
    for (int t = 0; t < (BM * D / 4) / NTHREADS; ++t) {
        int lin = t * NTHREADS + tid;
        int r = lin >> 5, c4 = lin & 31;
        *(float4*)(Xi + r * XI_STRIDE + c4 * 4) =
            *(const float4*)(P + (row0 + r) * D + c4 * 4);
    }

    const int rg  = tid >> 5, cg  = tid & 31;
    const int rg2 = tid >> 4, cg2 = tid & 15;

    float acc[2][8];
    #pragma unroll
    for (int i = 0; i < 2; i++)
        #pragma unroll
        for (int u = 0; u < 8; u++) acc[i][u] = 0.0f;
    float rs[4] = {0.f, 0.f, 0.f, 0.f};

    float sqi[4];
    #pragma unroll
    for (int i = 0; i < 4; i++) sqi[i] = g_sq[row0 + 4 * rg + i];

    const int ntiles = n / BN;
    for (int tile = 0; tile < ntiles; ++tile) {
        __syncthreads();
        const int j0 = tile * BN;
        #pragma unroll
        for (int t = 0; t < 16; ++t) {
            int lin = t * NTHREADS + tid;
            int r = lin >> 5, c4 = lin & 31;
            *(float4*)(Xj + r * XJ_STRIDE + c4 * 4) =
                *(const float4*)(P + (j0 + r) * D + c4 * 4);
        }
        __syncthreads();

        float s[4][4];
        #pragma unroll
        for (int i = 0; i < 4; i++)
            #pragma unroll
            for (int j = 0; j < 4; j++) s[i][j] = 0.0f;

        #pragma unroll 4
        for (int k4 = 0; k4 < 32; ++k4) {
            float4 a[4], b[4];
            #pragma unroll
            for (int i = 0; i < 4; i++)
                a[i] = *(const float4*)(Xi + (4 * rg + i) * XI_STRIDE + k4 * 4);
            #pragma unroll
            for (int j = 0; j < 4; j++)
                b[j] = *(const float4*)(Xj + (cg + 32 * j) * XJ_STRIDE + k4 * 4);
            #pragma unroll
            for (int i = 0; i < 4; i++)
                #pragma unroll
                for (int j = 0; j < 4; j++)
                    s[i][j] += a[i].x * b[j].x + a[i].y * b[j].y
                             + a[i].z * b[j].z + a[i].w * b[j].w;
        }

        float sqj[4];
        #pragma unroll
        for (int j = 0; j < 4; j++) sqj[j] = g_sq[j0 + cg + 32 * j];
        #pragma unroll
        for (int i = 0; i < 4; i++)
            #pragma unroll
            for (int j = 0; j < 4; j++) {
                float g = __expf((2.0f * s[i][j] - sqi[i] - sqj[j]) * inv2h2);
                rs[i] += g;
                Gs[(4 * rg + i) * GS_STRIDE + (cg + 32 * j)] = g;
            }
        __syncthreads();

        #pragma unroll 8
        for (int jj = 0; jj < BN; ++jj) {
            float g0 = Gs[(2 * rg2 + 0) * GS_STRIDE + jj];
            float g1 = Gs[(2 * rg2 + 1) * GS_STRIDE + jj];
            #pragma unroll
            for (int u = 0; u < 8; u++) {
                float x = Xj[jj * XJ_STRIDE + cg2 + 16 * u];
                acc[0][u] += g0 * x;
                acc[1][u] += g1 * x;
            }
        }
    }

    #pragma unroll
    for (int i = 0; i < 4; i++)
        #pragma unroll
        for (int o = 16; o > 0; o >>= 1)
            rs[i] += __shfl_xor_sync(0xffffffffu, rs[i], o);
    if (cg == 0)
        #pragma unroll
        for (int i = 0; i < 4; i++) rowsum[4 * rg + i] = rs[i];
    __syncthreads();

    const float invn = 1.0f / (float)n;
    #pragma unroll
    for (int i = 0; i < 2; i++) {
        int r = 2 * rg2 + i;
        float rsum = rowsum[r];
        #pragma unroll
        for (int u = 0; u < 8; u++) {
            int c = cg2 + 16 * u;
            float GP = acc[i][u];
            float x  = Xi[r * XI_STRIDE + c];
            out[(row0 + r) * D + c] =
                (rsum * mu[c] - GP - (x * rsum - GP) * invh2) * invn;
        }
    }
}

// ---------------------------------------------------------------------------
extern "C" void kernel_launch(void* const* d_in, const int* in_sizes, int n_in,
                              void* d_out, int out_size) {
    const float* P  = (const float*)d_in[0];
    const float* mu = (const float*)d_in[1];
    const float* bw = (const float*)d_in[2];
    float* out = (float*)d_out;
    const int n = in_sizes[0] / D;
    const int fast_ok = (n == NMAX) ? 1 : 0;

    const size_t fp32_smem =
        (size_t)(BM * XI_STRIDE + BN * XJ_STRIDE + BM * GS_STRIDE + BM) * sizeof(float);
    cudaFuncSetAttribute(svgd_fp32_kernel, cudaFuncAttributeMaxDynamicSharedMemorySize,
                         (int)fp32_smem);
    cudaFuncSetAttribute(svgd_hmma_kernel, cudaFuncAttributeMaxDynamicSharedMemorySize,
                         SM_TOTAL);

    prep_kernel<<<(n / 4 + 7) / 8, 256>>>(P, n);
    svgd_fp32_kernel<<<n / BM, NTHREADS, fp32_smem>>>(P, mu, bw, out, n, fast_ok);
    if (fast_ok) {
        svgd_hmma_kernel<<<dim3(NMAX / 128, JSPLIT), 256, SM_TOTAL>>>(bw);
        finish_kernel<<<(NMAX * D / 4 + 255) / 256, 256>>>(P, mu, bw, out, NMAX);
    }
}

// round 7
// speedup vs baseline: 1.2310x; 1.0146x over previous
#include <cuda_runtime.h>
#include <cuda_bf16.h>
#include <cstdint>

// ============================================================================
// SVGD: phi_i = (r_i*mu - GP_i - (x_i*r_i - GP_i)/h^2) / N
// When h^2 == 1 the GP terms cancel: phi_i = r_i*(mu - x_i)/N, so only the
// gram row-sum is needed. Fast path: bf16 HMMA (mma.sync.m16n8k16) S = X X^T
// with fp32 accumulation + exact diagonal fix (g_ii = 1). Generic-h path:
// proven fp32 fused kernel (early-exits when the fast path is active).
// R7 == R6 resubmit (R6 bench was an infra failure, no metrics):
// JSPLIT=8 + single-buffered Xj -> ~68KB smem -> 2 CTAs/SM so one CTA's
// HMMA overlaps the other's MUFU epilogue; next-tile cp.async overlapped with
// the epilogue; g_rpart transposed to [row][8] for vector loads in finish.
// tcgen05 does NOT assemble under this harness (plain sm_100 target).
// ============================================================================

#define D       128
#define NMAX    4096
#define JSPLIT  8
#define JSLICE  (NMAX / JSPLIT)   // 512
#define NT      (JSLICE / 128)    // 4 j-subtiles per CTA
#define LOG2E   1.4426950408889634f

__device__ float         g_sq[NMAX];
__device__ __nv_bfloat16 g_xbf[NMAX * D];
__device__ float         g_rpart[NMAX][JSPLIT];   // row-major: 32B per row

// ---------------------------------------------------------------------------
// PTX helpers
// ---------------------------------------------------------------------------
__device__ __forceinline__ uint32_t smem_u32(const void* p) {
    uint32_t a;
    asm("{ .reg .u64 t; cvta.to.shared.u64 t, %1; cvt.u32.u64 %0, t; }"
        : "=r"(a) : "l"(p));
    return a;
}
__device__ __forceinline__ void cp16(uint32_t dst, const void* src) {
    asm volatile("cp.async.cg.shared.global [%0], [%1], 16;" :: "r"(dst), "l"(src));
}
#define CP_COMMIT() asm volatile("cp.async.commit_group;" ::: "memory")
#define CP_WAIT0()  asm volatile("cp.async.wait_group 0;" ::: "memory")

__device__ __forceinline__ void ldsm4(uint32_t* r, uint32_t addr) {
    asm volatile("ldmatrix.sync.aligned.m8n8.x4.shared.b16 {%0,%1,%2,%3}, [%4];"
                 : "=r"(r[0]), "=r"(r[1]), "=r"(r[2]), "=r"(r[3]) : "r"(addr));
}
__device__ __forceinline__ void mma_bf16(float* c, const uint32_t* a,
                                         uint32_t b0, uint32_t b1) {
    asm volatile("mma.sync.aligned.m16n8k16.row.col.f32.bf16.bf16.f32 "
                 "{%0,%1,%2,%3}, {%4,%5,%6,%7}, {%8,%9}, {%0,%1,%2,%3};"
                 : "+f"(c[0]), "+f"(c[1]), "+f"(c[2]), "+f"(c[3])
                 : "r"(a[0]), "r"(a[1]), "r"(a[2]), "r"(a[3]), "r"(b0), "r"(b1));
}
__device__ __forceinline__ float exp2a(float x) {
    float g;
    asm("ex2.approx.ftz.f32 %0, %1;" : "=f"(g) : "f"(x));
    return g;
}

// ---------------------------------------------------------------------------
// Kernel 1: |x_i|^2 + bf16 copy of X. One warp per 4 rows, MLP=4.
// ---------------------------------------------------------------------------
__global__ void prep_kernel(const float* __restrict__ P, int n) {
    const int warp = (blockIdx.x * blockDim.x + threadIdx.x) >> 5;
    const int lane = threadIdx.x & 31;
    const int row0 = warp * 4;
    if (row0 >= n) return;

    float4 v[4];
    #pragma unroll
    for (int r = 0; r < 4; ++r)
        v[r] = *((const float4*)(P + (row0 + r) * D) + lane);

    float s[4];
    #pragma unroll
    for (int r = 0; r < 4; ++r)
        s[r] = v[r].x * v[r].x + v[r].y * v[r].y + v[r].z * v[r].z + v[r].w * v[r].w;

    #pragma unroll
    for (int o = 16; o > 0; o >>= 1) {
        #pragma unroll
        for (int r = 0; r < 4; ++r)
            s[r] += __shfl_xor_sync(0xffffffffu, s[r], o);
    }
    if (lane < 4) g_sq[row0 + lane] = s[lane];

    #pragma unroll
    for (int r = 0; r < 4; ++r) {
        __nv_bfloat162 p0 = __floats2bfloat162_rn(v[r].x, v[r].y);
        __nv_bfloat162 p1 = __floats2bfloat162_rn(v[r].z, v[r].w);
        ((__nv_bfloat162*)g_xbf)[(row0 + r) * 64 + lane * 2 + 0] = p0;
        ((__nv_bfloat162*)g_xbf)[(row0 + r) * 64 + lane * 2 + 1] = p1;
    }
}

// ---------------------------------------------------------------------------
// HMMA fast path (h^2==1): r_i = sum_j exp((2 S_ij - sq_i - sq_j)/2), diag = 1.
// grid (32, JSPLIT), 256 threads, 2 CTAs/SM. Warp layout: 2 (m) x 4 (n).
// SMEM tiles: 128 rows x 256B, 16B chunks XOR-swizzled (c ^ (r&7)).
// Single Xj buffer; next-tile cp.async overlaps the exp epilogue.
// ---------------------------------------------------------------------------
#define SM_XI    0
#define SM_XJ    32768
#define SM_RBUF  65536           // 128 floats
#define SM_CSL   66048           // JSLICE=512 floats
#define SM_TOTAL 68096

__device__ __forceinline__ void load_tile_async(uint32_t dst_sb, int src_row, int tid) {
    const char* src = (const char*)(g_xbf + (size_t)src_row * D);
    #pragma unroll
    for (int tt = 0; tt < 8; ++tt) {
        int lin = tt * 256 + tid;
        int r = lin >> 4, c = lin & 15;
        cp16(dst_sb + r * 256 + ((c ^ (r & 7)) << 4), src + r * 256 + c * 16);
    }
}

__global__ __launch_bounds__(256, 2)
void svgd_hmma_kernel(const float* __restrict__ bw) {
    const float h2 = bw[0] * bw[0];
    if (h2 != 1.0f) return;          // generic h handled by fp32 kernel

    extern __shared__ char smem[];
    const uint32_t sb = smem_u32(smem);
    float* rbuf = (float*)(smem + SM_RBUF);
    float* csl  = (float*)(smem + SM_CSL);

    const int tid   = threadIdx.x;
    const int wid   = tid >> 5;
    const int lane  = tid & 31;
    const int wm    = wid & 1;       // m half (64 rows)
    const int wn    = wid >> 1;      // n quarter (32 cols)
    const int row0  = blockIdx.x * 128;
    const int jbase = blockIdx.y * JSLICE;

    const float k2    = (0.5f / h2) * LOG2E;
    const float twok2 = 2.0f * k2;

    if (tid < 128) rbuf[tid] = 0.0f;
    for (int j = tid; j < JSLICE; j += 256) csl[j] = -g_sq[jbase + j] * k2;

    load_tile_async(sb + SM_XI, row0, tid);
    load_tile_async(sb + SM_XJ, jbase, tid);
    CP_COMMIT();

    // per-thread row constants: rows wm*64 + mt*16 + (lane>>2) + {0,8}
    const int r_in = lane >> 2;
    const int c2   = (lane & 3) * 2;
    float cti[8], rp[8];
    #pragma unroll
    for (int i = 0; i < 8; ++i) {
        int rloc = wm * 64 + (i >> 1) * 16 + r_in + (i & 1) * 8;
        cti[i] = -g_sq[row0 + rloc] * k2;
        rp[i]  = 0.0f;
    }

    CP_WAIT0();
    __syncthreads();

    const uint32_t xi_base = sb + SM_XI + (uint32_t)(wm * 64) * 256;
    const uint32_t xj_base = sb + SM_XJ + (uint32_t)(wn * 32) * 256;
    const uint32_t lrow16  = (uint32_t)(lane & 15) * 256;
    const uint32_t lswz    = (uint32_t)(lane & 7);
    const uint32_t lkhalf  = (uint32_t)(lane >> 4);

    for (int t = 0; t < NT; ++t) {
        // ---- S tile: 128 HMMA per warp, K=128 in 8 steps ----
        float acc[4][4][4];
        #pragma unroll
        for (int mt = 0; mt < 4; ++mt)
            #pragma unroll
            for (int nt = 0; nt < 4; ++nt)
                #pragma unroll
                for (int q = 0; q < 4; ++q) acc[mt][nt][q] = 0.0f;

        #pragma unroll
        for (int kk = 0; kk < 8; ++kk) {
            const uint32_t swz = (((uint32_t)(2 * kk) + lkhalf) ^ lswz) << 4;
            uint32_t a[4][4], b[2][4];
            #pragma unroll
            for (int mt = 0; mt < 4; ++mt)
                ldsm4(a[mt], xi_base + (uint32_t)(mt * 16) * 256 + lrow16 + swz);
            #pragma unroll
            for (int bt = 0; bt < 2; ++bt)
                ldsm4(b[bt], xj_base + (uint32_t)(bt * 16) * 256 + lrow16 + swz);
            #pragma unroll
            for (int mt = 0; mt < 4; ++mt) {
                mma_bf16(acc[mt][0], a[mt], b[0][0], b[0][2]);
                mma_bf16(acc[mt][1], a[mt], b[0][1], b[0][3]);
                mma_bf16(acc[mt][2], a[mt], b[1][0], b[1][2]);
                mma_bf16(acc[mt][3], a[mt], b[1][1], b[1][3]);
            }
        }

        // all warps done reading Xj -> start next tile's copy, then do the
        // exp epilogue while the cp.async is in flight.
        __syncthreads();
        if (t + 1 < NT) {
            load_tile_async(sb + SM_XJ, jbase + (t + 1) * 128, tid);
            CP_COMMIT();
        }

        // ---- epilogue: g = exp2((2S - sqi - sqj)*log2e/2), diag forced 1 ----
        const bool diag = (jbase + t * 128 == row0);
        #pragma unroll
        for (int mt = 0; mt < 4; ++mt) {
            const int rloc0 = wm * 64 + mt * 16 + r_in;
            const int rloc1 = rloc0 + 8;
            const float ct0 = cti[mt * 2], ct1 = cti[mt * 2 + 1];
            #pragma unroll
            for (int nt = 0; nt < 4; ++nt) {
                const int cloc = wn * 32 + nt * 8 + c2;
                float2 cs = *(float2*)(csl + t * 128 + cloc);
                float g0 = exp2a(fmaf(acc[mt][nt][0], twok2, ct0 + cs.x));
                float g1 = exp2a(fmaf(acc[mt][nt][1], twok2, ct0 + cs.y));
                float g2 = exp2a(fmaf(acc[mt][nt][2], twok2, ct1 + cs.x));
                float g3 = exp2a(fmaf(acc[mt][nt][3], twok2, ct1 + cs.y));
                if (diag) {
                    if (rloc0 == cloc)     g0 = 1.0f;
                    if (rloc0 == cloc + 1) g1 = 1.0f;
                    if (rloc1 == cloc)     g2 = 1.0f;
                    if (rloc1 == cloc + 1) g3 = 1.0f;
                }
                rp[mt * 2]     += g0 + g1;
                rp[mt * 2 + 1] += g2 + g3;
            }
        }

        if (t + 1 < NT) CP_WAIT0();
        __syncthreads();
    }

    // ---- reduce across the 4 column lanes, then across n-warps via smem ----
    #pragma unroll
    for (int i = 0; i < 8; ++i) {
        rp[i] += __shfl_xor_sync(0xffffffffu, rp[i], 1);
        rp[i] += __shfl_xor_sync(0xffffffffu, rp[i], 2);
    }
    if ((lane & 3) == 0) {
        #pragma unroll
        for (int i = 0; i < 8; ++i) {
            int rloc = wm * 64 + (i >> 1) * 16 + r_in + (i & 1) * 8;
            atomicAdd(&rbuf[rloc], rp[i]);
        }
    }
    __syncthreads();
    if (tid < 128) g_rpart[row0 + tid][blockIdx.y] = rbuf[tid];
}

// ---------------------------------------------------------------------------
// Finish (h^2 == 1): out = r * (mu - x) / n. One float4 of output per thread;
// the 8 row partials arrive as two LDG.128.
// ---------------------------------------------------------------------------
__global__ void finish_kernel(const float* __restrict__ P, const float* __restrict__ mu,
                              const float* __restrict__ bw, float* __restrict__ out, int n) {
    float h2 = bw[0] * bw[0];
    if (h2 != 1.0f) return;
    int gid = blockIdx.x * blockDim.x + threadIdx.x;   // float4 index
    if (gid >= n * (D / 4)) return;
    int i  = gid >> 5;          // row (32 float4 per row)
    int c4 = (gid & 31) * 4;
    float4 r0 = *(const float4*)&g_rpart[i][0];
    float4 r1 = *(const float4*)&g_rpart[i][4];
    float4 xv = *(const float4*)(P  + i * D + c4);
    float4 mv = *(const float4*)(mu + c4);
    float r = (r0.x + r0.y) + (r0.z + r0.w) + (r1.x + r1.y) + (r1.z + r1.w);
    float s = r * (1.0f / (float)n);
    float4 o;
    o.x = (mv.x - xv.x) * s;
    o.y = (mv.y - xv.y) * s;
    o.z = (mv.z - xv.z) * s;
    o.w = (mv.w - xv.w) * s;
    *(float4*)(out + i * D + c4) = o;
}

// ---------------------------------------------------------------------------
// Generic-h fp32 fallback (proven R1 kernel). Early-exits when h^2==1.
// ---------------------------------------------------------------------------
#define BM        32
#define BN        128
#define NTHREADS  256
#define XI_STRIDE 132
#define XJ_STRIDE 132
#define GS_STRIDE 132

__global__ __launch_bounds__(NTHREADS, 1)
void svgd_fp32_kernel(const float* __restrict__ P, const float* __restrict__ mu,
                      const float* __restrict__ bw, float* __restrict__ out,
                      int n, int tensor_active) {
    const float h2 = bw[0] * bw[0];
    if (tensor_active && h2 == 1.0f) return;

    extern __shared__ float sm[];
    float* Xi     = sm;
    float* Xj     = Xi + BM * XI_STRIDE;
    float* Gs     = Xj + BN * XJ_STRIDE;
    float* rowsum = Gs + BM * GS_STRIDE;

    const int tid  = threadIdx.x;
    const int row0 = blockIdx.x * BM;
    const float inv2h2 = 1.0f / (2.0f * h2);
    const float invh2  = 1.0f / h2;

    #pragma unroll
    for (int t = 0; t < (BM * D / 4) / NTHREADS; ++t) {
        int lin = t * NTHREADS + tid;
        int r = lin >> 5, c4 = lin & 31;
        *(float4*)(Xi + r * XI_STRIDE + c4 * 4) =
            *(const float4*)(P + (row0 + r) * D + c4 * 4);
    }

    const int rg  = tid >> 5, cg  = tid & 31;
    const int rg2 = tid >> 4, cg2 = tid & 15;

    float acc[2][8];
    #pragma unroll
    for (int i = 0; i < 2; i++)
        #pragma unroll
        for (int u = 0; u < 8; u++) acc[i][u] = 0.0f;
    float rs[4] = {0.f, 0.f, 0.f, 0.f};

    float sqi[4];
    #pragma unroll
    for (int i = 0; i < 4; i++) sqi[i] = g_sq[row0 + 4 * rg + i];

    const int ntiles = n / BN;
    for (int tile = 0; tile < ntiles; ++tile) {
        __syncthreads();
        const int j0 = tile * BN;
        #pragma unroll
        for (int t = 0; t < 16; ++t) {
            int lin = t * NTHREADS + tid;
            int r = lin >> 5, c4 = lin & 31;
            *(float4*)(Xj + r * XJ_STRIDE + c4 * 4) =
                *(const float4*)(P + (j0 + r) * D + c4 * 4);
        }
        __syncthreads();

        float s[4][4];
        #pragma unroll
        for (int i = 0; i < 4; i++)
            #pragma unroll
            for (int j = 0; j < 4; j++) s[i][j] = 0.0f;

        #pragma unroll 4
        for (int k4 = 0; k4 < 32; ++k4) {
            float4 a[4], b[4];
            #pragma unroll
            for (int i = 0; i < 4; i++)
                a[i] = *(const float4*)(Xi + (4 * rg + i) * XI_STRIDE + k4 * 4);
            #pragma unroll
            for (int j = 0; j < 4; j++)
                b[j] = *(const float4*)(Xj + (cg + 32 * j) * XJ_STRIDE + k4 * 4);
            #pragma unroll
            for (int i = 0; i < 4; i++)
                #pragma unroll
                for (int j = 0; j < 4; j++)
                    s[i][j] += a[i].x * b[j].x + a[i].y * b[j].y
                             + a[i].z * b[j].z + a[i].w * b[j].w;
        }

        float sqj[4];
        #pragma unroll
        for (int j = 0; j < 4; j++) sqj[j] = g_sq[j0 + cg + 32 * j];
        #pragma unroll
        for (int i = 0; i < 4; i++)
            #pragma unroll
            for (int j = 0; j < 4; j++) {
                float g = __expf((2.0f * s[i][j] - sqi[i] - sqj[j]) * inv2h2);
                rs[i] += g;
                Gs[(4 * rg + i) * GS_STRIDE + (cg + 32 * j)] = g;
            }
        __syncthreads();

        #pragma unroll 8
        for (int jj = 0; jj < BN; ++jj) {
            float g0 = Gs[(2 * rg2 + 0) * GS_STRIDE + jj];
            float g1 = Gs[(2 * rg2 + 1) * GS_STRIDE + jj];
            #pragma unroll
            for (int u = 0; u < 8; u++) {
                float x = Xj[jj * XJ_STRIDE + cg2 + 16 * u];
                acc[0][u] += g0 * x;
                acc[1][u] += g1 * x;
            }
        }
    }

    #pragma unroll
    for (int i = 0; i < 4; i++)
        #pragma unroll
        for (int o = 16; o > 0; o >>= 1)
            rs[i] += __shfl_xor_sync(0xffffffffu, rs[i], o);
    if (cg == 0)
        #pragma unroll
        for (int i = 0; i < 4; i++) rowsum[4 * rg + i] = rs[i];
    __syncthreads();

    const float invn = 1.0f / (float)n;
    #pragma unroll
    for (int i = 0; i < 2; i++) {
        int r = 2 * rg2 + i;
        float rsum = rowsum[r];
        #pragma unroll
        for (int u = 0; u < 8; u++) {
            int c = cg2 + 16 * u;
            float GP = acc[i][u];
            float x  = Xi[r * XI_STRIDE + c];
            out[(row0 + r) * D + c] =
                (rsum * mu[c] - GP - (x * rsum - GP) * invh2) * invn;
        }
    }
}

// ---------------------------------------------------------------------------
extern "C" void kernel_launch(void* const* d_in, const int* in_sizes, int n_in,
                              void* d_out, int out_size) {
    const float* P  = (const float*)d_in[0];
    const float* mu = (const float*)d_in[1];
    const float* bw = (const float*)d_in[2];
    float* out = (float*)d_out;
    const int n = in_sizes[0] / D;
    const int fast_ok = (n == NMAX) ? 1 : 0;

    const size_t fp32_smem =
        (size_t)(BM * XI_STRIDE + BN * XJ_STRIDE + BM * GS_STRIDE + BM) * sizeof(float);
    cudaFuncSetAttribute(svgd_fp32_kernel, cudaFuncAttributeMaxDynamicSharedMemorySize,
                         (int)fp32_smem);
    cudaFuncSetAttribute(svgd_hmma_kernel, cudaFuncAttributeMaxDynamicSharedMemorySize,
                         SM_TOTAL);

    prep_kernel<<<(n / 4 + 7) / 8, 256>>>(P, n);
    svgd_fp32_kernel<<<n / BM, NTHREADS, fp32_smem>>>(P, mu, bw, out, n, fast_ok);
    if (fast_ok) {
        svgd_hmma_kernel<<<dim3(NMAX / 128, JSPLIT), 256, SM_TOTAL>>>(bw);
        finish_kernel<<<(NMAX * D / 4 + 255) / 256, 256>>>(P, mu, bw, out, NMAX);
    }
}

// round 8
// speedup vs baseline: 1.4357x; 1.1663x over previous
#include <cuda_runtime.h>
#include <cuda_bf16.h>
#include <cstdint>

// ============================================================================
// SVGD: phi_i = (r_i*mu - GP_i - (x_i*r_i - GP_i)/h^2) / N
// When h^2 == 1 the GP terms cancel: phi_i = r_i*(mu - x_i)/N, so only the
// gram row-sum is needed. Fast path: bf16 HMMA (mma.sync.m16n8k16) S = X X^T
// with fp32 accumulation + exact diagonal fix (g_ii = 1).
// R8: (a) exp-threshold epilogue -- args computed via FMA (overlaps tensor
// pipe); a tile whose max arg (log2 units) is < -60 contributes < 2^-51 to a
// row-sum of ~1, so only diagonal-containing tiles run MUFU ex2 (32x fewer).
// (b) generic-h fp32 fallback folded into the hmma kernel (blockIdx.y<4 CTAs)
// -> 3 launches on the fast path. (c) finish batches 4 rows/thread (MLP~12).
// tcgen05 does NOT assemble under this harness (plain sm_100 target).
// ============================================================================

#define D       128
#define NMAX    4096
#define JSPLIT  8
#define JSLICE  (NMAX / JSPLIT)   // 512
#define NT      (JSLICE / 128)    // 4 j-subtiles per CTA
#define LOG2E   1.4426950408889634f

__device__ float         g_sq[NMAX];
__device__ __nv_bfloat16 g_xbf[NMAX * D];
__device__ float         g_rpart[NMAX][JSPLIT];   // row-major: 32B per row

// ---------------------------------------------------------------------------
// PTX helpers
// ---------------------------------------------------------------------------
__device__ __forceinline__ uint32_t smem_u32(const void* p) {
    uint32_t a;
    asm("{ .reg .u64 t; cvta.to.shared.u64 t, %1; cvt.u32.u64 %0, t; }"
        : "=r"(a) : "l"(p));
    return a;
}
__device__ __forceinline__ void cp16(uint32_t dst, const void* src) {
    asm volatile("cp.async.cg.shared.global [%0], [%1], 16;" :: "r"(dst), "l"(src));
}
#define CP_COMMIT() asm volatile("cp.async.commit_group;" ::: "memory")
#define CP_WAIT0()  asm volatile("cp.async.wait_group 0;" ::: "memory")

__device__ __forceinline__ void ldsm4(uint32_t* r, uint32_t addr) {
    asm volatile("ldmatrix.sync.aligned.m8n8.x4.shared.b16 {%0,%1,%2,%3}, [%4];"
                 : "=r"(r[0]), "=r"(r[1]), "=r"(r[2]), "=r"(r[3]) : "r"(addr));
}
__device__ __forceinline__ void mma_bf16(float* c, const uint32_t* a,
                                         uint32_t b0, uint32_t b1) {
    asm volatile("mma.sync.aligned.m16n8k16.row.col.f32.bf16.bf16.f32 "
                 "{%0,%1,%2,%3}, {%4,%5,%6,%7}, {%8,%9}, {%0,%1,%2,%3};"
                 : "+f"(c[0]), "+f"(c[1]), "+f"(c[2]), "+f"(c[3])
                 : "r"(a[0]), "r"(a[1]), "r"(a[2]), "r"(a[3]), "r"(b0), "r"(b1));
}
__device__ __forceinline__ float exp2a(float x) {
    float g;
    asm("ex2.approx.ftz.f32 %0, %1;" : "=f"(g) : "f"(x));
    return g;
}

// ---------------------------------------------------------------------------
// Kernel 1: |x_i|^2 + bf16 copy of X. One warp per 4 rows, MLP=4.
// ---------------------------------------------------------------------------
__global__ void prep_kernel(const float* __restrict__ P, int n) {
    const int warp = (blockIdx.x * blockDim.x + threadIdx.x) >> 5;
    const int lane = threadIdx.x & 31;
    const int row0 = warp * 4;
    if (row0 >= n) return;

    float4 v[4];
    #pragma unroll
    for (int r = 0; r < 4; ++r)
        v[r] = *((const float4*)(P + (row0 + r) * D) + lane);

    float s[4];
    #pragma unroll
    for (int r = 0; r < 4; ++r)
        s[r] = v[r].x * v[r].x + v[r].y * v[r].y + v[r].z * v[r].z + v[r].w * v[r].w;

    #pragma unroll
    for (int o = 16; o > 0; o >>= 1) {
        #pragma unroll
        for (int r = 0; r < 4; ++r)
            s[r] += __shfl_xor_sync(0xffffffffu, s[r], o);
    }
    if (lane < 4) g_sq[row0 + lane] = s[lane];

    #pragma unroll
    for (int r = 0; r < 4; ++r) {
        __nv_bfloat162 p0 = __floats2bfloat162_rn(v[r].x, v[r].y);
        __nv_bfloat162 p1 = __floats2bfloat162_rn(v[r].z, v[r].w);
        ((__nv_bfloat162*)g_xbf)[(row0 + r) * 64 + lane * 2 + 0] = p0;
        ((__nv_bfloat162*)g_xbf)[(row0 + r) * 64 + lane * 2 + 1] = p1;
    }
}

// ---------------------------------------------------------------------------
// Generic-h fp32 block (proven R1 math), used by the fallback paths.
// Processes rows [row0, row0+32) against all n columns. sm = 37KB scratch.
// ---------------------------------------------------------------------------
#define BM        32
#define BN        128
#define XI_STRIDE 132
#define XJ_STRIDE 132
#define GS_STRIDE 132

__device__ void fp32_block(const float* __restrict__ P, const float* __restrict__ mu,
                           float* __restrict__ out, int n, int row0, float h2,
                           float* sm, int tid) {
    float* Xi     = sm;
    float* Xj     = Xi + BM * XI_STRIDE;
    float* Gs     = Xj + BN * XJ_STRIDE;
    float* rowsum = Gs + BM * GS_STRIDE;

    const float inv2h2 = 1.0f / (2.0f * h2);
    const float invh2  = 1.0f / h2;

    #pragma unroll
    for (int t = 0; t < 4; ++t) {
        int lin = t * 256 + tid;
        int r = lin >> 5, c4 = lin & 31;
        *(float4*)(Xi + r * XI_STRIDE + c4 * 4) =
            *(const float4*)(P + (row0 + r) * D + c4 * 4);
    }

    const int rg  = tid >> 5, cg  = tid & 31;
    const int rg2 = tid >> 4, cg2 = tid & 15;

    float acc[2][8];
    #pragma unroll
    for (int i = 0; i < 2; i++)
        #pragma unroll
        for (int u = 0; u < 8; u++) acc[i][u] = 0.0f;
    float rs[4] = {0.f, 0.f, 0.f, 0.f};

    float sqi[4];
    #pragma unroll
    for (int i = 0; i < 4; i++) sqi[i] = g_sq[row0 + 4 * rg + i];

    const int ntiles = n / BN;
    for (int tile = 0; tile < ntiles; ++tile) {
        __syncthreads();
        const int j0 = tile * BN;
        #pragma unroll
        for (int t = 0; t < 16; ++t) {
            int lin = t * 256 + tid;
            int r = lin >> 5, c4 = lin & 31;
            *(float4*)(Xj + r * XJ_STRIDE + c4 * 4) =
                *(const float4*)(P + (j0 + r) * D + c4 * 4);
        }
        __syncthreads();

        float s[4][4];
        #pragma unroll
        for (int i = 0; i < 4; i++)
            #pragma unroll
            for (int j = 0; j < 4; j++) s[i][j] = 0.0f;

        #pragma unroll 4
        for (int k4 = 0; k4 < 32; ++k4) {
            float4 a[4], b[4];
            #pragma unroll
            for (int i = 0; i < 4; i++)
                a[i] = *(const float4*)(Xi + (4 * rg + i) * XI_STRIDE + k4 * 4);
            #pragma unroll
            for (int j = 0; j < 4; j++)
                b[j] = *(const float4*)(Xj + (cg + 32 * j) * XJ_STRIDE + k4 * 4);
            #pragma unroll
            for (int i = 0; i < 4; i++)
                #pragma unroll
                for (int j = 0; j < 4; j++)
                    s[i][j] += a[i].x * b[j].x + a[i].y * b[j].y
                             + a[i].z * b[j].z + a[i].w * b[j].w;
        }

        float sqj[4];
        #pragma unroll
        for (int j = 0; j < 4; j++) sqj[j] = g_sq[j0 + cg + 32 * j];
        #pragma unroll
        for (int i = 0; i < 4; i++)
            #pragma unroll
            for (int j = 0; j < 4; j++) {
                float g = __expf((2.0f * s[i][j] - sqi[i] - sqj[j]) * inv2h2);
                rs[i] += g;
                Gs[(4 * rg + i) * GS_STRIDE + (cg + 32 * j)] = g;
            }
        __syncthreads();

        #pragma unroll 8
        for (int jj = 0; jj < BN; ++jj) {
            float g0 = Gs[(2 * rg2 + 0) * GS_STRIDE + jj];
            float g1 = Gs[(2 * rg2 + 1) * GS_STRIDE + jj];
            #pragma unroll
            for (int u = 0; u < 8; u++) {
                float x = Xj[jj * XJ_STRIDE + cg2 + 16 * u];
                acc[0][u] += g0 * x;
                acc[1][u] += g1 * x;
            }
        }
    }

    #pragma unroll
    for (int i = 0; i < 4; i++)
        #pragma unroll
        for (int o = 16; o > 0; o >>= 1)
            rs[i] += __shfl_xor_sync(0xffffffffu, rs[i], o);
    if (cg == 0)
        #pragma unroll
        for (int i = 0; i < 4; i++) rowsum[4 * rg + i] = rs[i];
    __syncthreads();

    const float invn = 1.0f / (float)n;
    #pragma unroll
    for (int i = 0; i < 2; i++) {
        int r = 2 * rg2 + i;
        float rsum = rowsum[r];
        #pragma unroll
        for (int u = 0; u < 8; u++) {
            int c = cg2 + 16 * u;
            float GP = acc[i][u];
            float x  = Xi[r * XI_STRIDE + c];
            out[(row0 + r) * D + c] =
                (rsum * mu[c] - GP - (x * rsum - GP) * invh2) * invn;
        }
    }
}

// ---------------------------------------------------------------------------
// HMMA fast path (h^2==1): r_i = sum_j exp((2 S_ij - sq_i - sq_j)/2), diag = 1.
// grid (32, JSPLIT), 256 threads, 2 CTAs/SM. Warp layout: 2 (m) x 4 (n).
// SMEM tiles: 128 rows x 256B, 16B chunks XOR-swizzled (c ^ (r&7)).
// Epilogue: FMA args + FMNMX tile-max; MUFU ex2 only when max > -60 (in log2
// units) -- i.e. only diagonal-containing tiles.
// If h^2 != 1: CTAs with blockIdx.y<4 each run one generic fp32 32-row block.
// ---------------------------------------------------------------------------
#define SM_XI    0
#define SM_XJ    32768
#define SM_RBUF  65536           // 128 floats
#define SM_CSL   66048           // JSLICE=512 floats
#define SM_TOTAL 68096

__device__ __forceinline__ void load_tile_async(uint32_t dst_sb, int src_row, int tid) {
    const char* src = (const char*)(g_xbf + (size_t)src_row * D);
    #pragma unroll
    for (int tt = 0; tt < 8; ++tt) {
        int lin = tt * 256 + tid;
        int r = lin >> 4, c = lin & 15;
        cp16(dst_sb + r * 256 + ((c ^ (r & 7)) << 4), src + r * 256 + c * 16);
    }
}

__global__ __launch_bounds__(256, 2)
void svgd_hmma_kernel(const float* __restrict__ P, const float* __restrict__ mu,
                      const float* __restrict__ bw, float* __restrict__ out) {
    extern __shared__ char smem[];
    const float h2 = bw[0] * bw[0];
    const int tid = threadIdx.x;

    if (h2 != 1.0f) {                 // generic-h fallback (never on dataset)
        if (blockIdx.y < 4) {
            int row0 = (blockIdx.x * 4 + blockIdx.y) * BM;
            fp32_block(P, mu, out, NMAX, row0, h2, (float*)smem, tid);
        }
        return;
    }

    const uint32_t sb = smem_u32(smem);
    float* rbuf = (float*)(smem + SM_RBUF);
    float* csl  = (float*)(smem + SM_CSL);

    const int wid   = tid >> 5;
    const int lane  = tid & 31;
    const int wm    = wid & 1;       // m half (64 rows)
    const int wn    = wid >> 1;      // n quarter (32 cols)
    const int row0  = blockIdx.x * 128;
    const int jbase = blockIdx.y * JSLICE;

    const float k2    = 0.5f * LOG2E;
    const float twok2 = 2.0f * k2;

    if (tid < 128) rbuf[tid] = 0.0f;
    for (int j = tid; j < JSLICE; j += 256) csl[j] = -g_sq[jbase + j] * k2;

    load_tile_async(sb + SM_XI, row0, tid);
    load_tile_async(sb + SM_XJ, jbase, tid);
    CP_COMMIT();

    // per-thread row constants: rows wm*64 + mt*16 + (lane>>2) + {0,8}
    const int r_in = lane >> 2;
    const int c2   = (lane & 3) * 2;
    float cti[8], rp[8];
    #pragma unroll
    for (int i = 0; i < 8; ++i) {
        int rloc = wm * 64 + (i >> 1) * 16 + r_in + (i & 1) * 8;
        cti[i] = -g_sq[row0 + rloc] * k2;
        rp[i]  = 0.0f;
    }

    CP_WAIT0();
    __syncthreads();

    const uint32_t xi_base = sb + SM_XI + (uint32_t)(wm * 64) * 256;
    const uint32_t xj_base = sb + SM_XJ + (uint32_t)(wn * 32) * 256;
    const uint32_t lrow16  = (uint32_t)(lane & 15) * 256;
    const uint32_t lswz    = (uint32_t)(lane & 7);
    const uint32_t lkhalf  = (uint32_t)(lane >> 4);

    for (int t = 0; t < NT; ++t) {
        // ---- S tile: 128 HMMA per warp, K=128 in 8 steps ----
        float acc[4][4][4];
        #pragma unroll
        for (int mt = 0; mt < 4; ++mt)
            #pragma unroll
            for (int nt = 0; nt < 4; ++nt)
                #pragma unroll
                for (int q = 0; q < 4; ++q) acc[mt][nt][q] = 0.0f;

        #pragma unroll
        for (int kk = 0; kk < 8; ++kk) {
            const uint32_t swz = (((uint32_t)(2 * kk) + lkhalf) ^ lswz) << 4;
            uint32_t a[4][4], b[2][4];
            #pragma unroll
            for (int mt = 0; mt < 4; ++mt)
                ldsm4(a[mt], xi_base + (uint32_t)(mt * 16) * 256 + lrow16 + swz);
            #pragma unroll
            for (int bt = 0; bt < 2; ++bt)
                ldsm4(b[bt], xj_base + (uint32_t)(bt * 16) * 256 + lrow16 + swz);
            #pragma unroll
            for (int mt = 0; mt < 4; ++mt) {
                mma_bf16(acc[mt][0], a[mt], b[0][0], b[0][2]);
                mma_bf16(acc[mt][1], a[mt], b[0][1], b[0][3]);
                mma_bf16(acc[mt][2], a[mt], b[1][0], b[1][2]);
                mma_bf16(acc[mt][3], a[mt], b[1][1], b[1][3]);
            }
        }

        // all warps done reading Xj -> start next tile's copy, then do the
        // epilogue while the cp.async is in flight.
        __syncthreads();
        if (t + 1 < NT) {
            load_tile_async(sb + SM_XJ, jbase + (t + 1) * 128, tid);
            CP_COMMIT();
        }

        // ---- epilogue: args in place (FMA pipe), tile max (ALU pipe) ----
        float tmax = -1e30f;
        #pragma unroll
        for (int mt = 0; mt < 4; ++mt) {
            const float ct0 = cti[mt * 2], ct1 = cti[mt * 2 + 1];
            #pragma unroll
            for (int nt = 0; nt < 4; ++nt) {
                const int cloc = wn * 32 + nt * 8 + c2;
                float2 cs = *(float2*)(csl + t * 128 + cloc);
                float a0 = fmaf(acc[mt][nt][0], twok2, ct0 + cs.x);
                float a1 = fmaf(acc[mt][nt][1], twok2, ct0 + cs.y);
                float a2 = fmaf(acc[mt][nt][2], twok2, ct1 + cs.x);
                float a3 = fmaf(acc[mt][nt][3], twok2, ct1 + cs.y);
                acc[mt][nt][0] = a0; acc[mt][nt][1] = a1;
                acc[mt][nt][2] = a2; acc[mt][nt][3] = a3;
                tmax = fmaxf(tmax, fmaxf(fmaxf(a0, a1), fmaxf(a2, a3)));
            }
        }

        // a tile with max arg < -60 (log2) contributes < 512*2^-60 ~ 4e-16
        // to a row-sum of ~1 -> skip the MUFU work entirely.
        if (tmax > -60.0f) {
            const bool diag = (jbase + t * 128 == row0);
            #pragma unroll
            for (int mt = 0; mt < 4; ++mt) {
                const int rloc0 = wm * 64 + mt * 16 + r_in;
                const int rloc1 = rloc0 + 8;
                #pragma unroll
                for (int nt = 0; nt < 4; ++nt) {
                    const int cloc = wn * 32 + nt * 8 + c2;
                    float g0 = exp2a(acc[mt][nt][0]);
                    float g1 = exp2a(acc[mt][nt][1]);
                    float g2 = exp2a(acc[mt][nt][2]);
                    float g3 = exp2a(acc[mt][nt][3]);
                    if (diag) {
                        if (rloc0 == cloc)     g0 = 1.0f;
                        if (rloc0 == cloc + 1) g1 = 1.0f;
                        if (rloc1 == cloc)     g2 = 1.0f;
                        if (rloc1 == cloc + 1) g3 = 1.0f;
                    }
                    rp[mt * 2]     += g0 + g1;
                    rp[mt * 2 + 1] += g2 + g3;
                }
            }
        }

        if (t + 1 < NT) CP_WAIT0();
        __syncthreads();
    }

    // ---- reduce across the 4 column lanes, then across n-warps via smem ----
    #pragma unroll
    for (int i = 0; i < 8; ++i) {
        rp[i] += __shfl_xor_sync(0xffffffffu, rp[i], 1);
        rp[i] += __shfl_xor_sync(0xffffffffu, rp[i], 2);
    }
    if ((lane & 3) == 0) {
        #pragma unroll
        for (int i = 0; i < 8; ++i) {
            int rloc = wm * 64 + (i >> 1) * 16 + r_in + (i & 1) * 8;
            atomicAdd(&rbuf[rloc], rp[i]);
        }
    }
    __syncthreads();
    if (tid < 128) g_rpart[row0 + tid][blockIdx.y] = rbuf[tid];
}

// ---------------------------------------------------------------------------
// Finish (h^2 == 1): out = r * (mu - x) / n. 4 rows x one float4 per thread
// (rows i, i+1024, i+2048, i+3072) -> ~12 front-batched LDG.
// ---------------------------------------------------------------------------
__global__ void finish_kernel(const float* __restrict__ P, const float* __restrict__ mu,
                              const float* __restrict__ bw, float* __restrict__ out, int n) {
    float h2 = bw[0] * bw[0];
    if (h2 != 1.0f) return;
    int gid = blockIdx.x * blockDim.x + threadIdx.x;   // [0, n*32/4)
    int c4 = (gid & 31) * 4;
    int i0 = gid >> 5;                                  // 0..n/4-1
    const int Q = n >> 2;

    float4 r0[4], r1[4], xv[4];
    #pragma unroll
    for (int k = 0; k < 4; ++k) {
        int i = i0 + k * Q;
        r0[k] = *(const float4*)&g_rpart[i][0];
        r1[k] = *(const float4*)&g_rpart[i][4];
        xv[k] = *(const float4*)(P + i * D + c4);
    }
    float4 mv = *(const float4*)(mu + c4);
    const float invn = 1.0f / (float)n;

    #pragma unroll
    for (int k = 0; k < 4; ++k) {
        int i = i0 + k * Q;
        float r = (r0[k].x + r0[k].y) + (r0[k].z + r0[k].w)
                + (r1[k].x + r1[k].y) + (r1[k].z + r1[k].w);
        float s = r * invn;
        float4 o;
        o.x = (mv.x - xv[k].x) * s;
        o.y = (mv.y - xv[k].y) * s;
        o.z = (mv.z - xv[k].z) * s;
        o.w = (mv.w - xv[k].w) * s;
        *(float4*)(out + i * D + c4) = o;
    }
}

// ---------------------------------------------------------------------------
// Standalone generic-h kernel for n != NMAX (dataset never takes this).
// ---------------------------------------------------------------------------
__global__ __launch_bounds__(256, 1)
void svgd_fp32_kernel(const float* __restrict__ P, const float* __restrict__ mu,
                      const float* __restrict__ bw, float* __restrict__ out, int n) {
    extern __shared__ float sm[];
    const float h2 = bw[0] * bw[0];
    fp32_block(P, mu, out, n, blockIdx.x * BM, h2, sm, threadIdx.x);
}

// ---------------------------------------------------------------------------
extern "C" void kernel_launch(void* const* d_in, const int* in_sizes, int n_in,
                              void* d_out, int out_size) {
    const float* P  = (const float*)d_in[0];
    const float* mu = (const float*)d_in[1];
    const float* bw = (const float*)d_in[2];
    float* out = (float*)d_out;
    const int n = in_sizes[0] / D;
    const int fast_ok = (n == NMAX) ? 1 : 0;

    const size_t fp32_smem =
        (size_t)(BM * XI_STRIDE + BN * XJ_STRIDE + BM * GS_STRIDE + BM) * sizeof(float);
    cudaFuncSetAttribute(svgd_fp32_kernel, cudaFuncAttributeMaxDynamicSharedMemorySize,
                         (int)fp32_smem);
    cudaFuncSetAttribute(svgd_hmma_kernel, cudaFuncAttributeMaxDynamicSharedMemorySize,
                         SM_TOTAL);

    prep_kernel<<<(n / 4 + 7) / 8, 256>>>(P, n);
    if (fast_ok) {
        svgd_hmma_kernel<<<dim3(NMAX / 128, JSPLIT), 256, SM_TOTAL>>>(P, mu, bw, out);
        finish_kernel<<<NMAX * 32 / 4 / 256, 256>>>(P, mu, bw, out, NMAX);
    } else {
        svgd_fp32_kernel<<<n / BM, 256, fp32_smem>>>(P, mu, bw, out, n);
    }
}